// round 6
// baseline (speedup 1.0000x reference)
#include <cuda_runtime.h>
#include <cuda_bf16.h>

// GradPooling: out[b,oh,ow,c] = sel ? max2x2 : mean2x2
//   sel = 2*(|x[oh+1,ow+1]-x[oh,ow+1]| + |x[oh+1,ow+1]-x[oh+1,ow]|) > lamb
//   pool window = x rows {2oh-1,2oh} x cols {2ow-1,2ow}, OOB -> 0.0
// x (32,224,224,64) f32 NHWC, out (32,112,112,64) f32.
//
// R5: R4 structure (ow-pair per thread, 13 loads) + __launch_bounds__(256,5)
//     to lift resident warps 32 -> 40 per SM. Compiler splits the load batch
//     (~10 + 3) to fit 51 regs; net in-flight loads/SM rise ~23%.

#define B_   32
#define H_   224
#define W_   224
#define C_   64
#define OH_  112
#define OW_  112
#define OJ_  (OW_ / 2)   // 56 ow-pairs
#define C4_  (C_ / 4)    // 16 float4 groups per pixel

__global__ __launch_bounds__(256, 5)
void gradpool_kernel(const float* __restrict__ x,
                     const float* __restrict__ lamb,
                     float* __restrict__ out)
{
    const int tid = blockIdx.x * blockDim.x + threadIdx.x;

    const int c4 = tid & (C4_ - 1);
    int t = tid >> 4;
    const int j  = t % OJ_;  t /= OJ_;
    const int oh = t % OH_;
    const int b  = t / OH_;

    const float lam = __ldg(lamb);

    const float4* xb = (const float4*)(x) + ((b * H_) * W_) * C4_ + c4;
    #define XV(h, w) xb[((h) * W_ + (w)) * C4_]

    // ---- pool windows: rows {2oh-1, 2oh}, cols {4j-1..4j+2} ----
    const int h0 = 2 * oh - 1;
    const int h1 = 2 * oh;
    const int w0 = 4 * j - 1;

    const float4 z = make_float4(0.f, 0.f, 0.f, 0.f);
    float4 a00 = z, a01, a02, a03;          // row h0
    float4 b00 = z, b01, b02, b03;          // row h1
    b01 = XV(h1, w0 + 1);
    b02 = XV(h1, w0 + 2);
    b03 = XV(h1, w0 + 3);
    if (j > 0) b00 = XV(h1, w0);
    if (oh > 0) {
        a01 = XV(h0, w0 + 1);
        a02 = XV(h0, w0 + 2);
        a03 = XV(h0, w0 + 3);
        if (j > 0) a00 = XV(h0, w0);
    } else {
        a01 = z; a02 = z; a03 = z;
    }

    // ---- gradient taps (rows oh..oh+1 <= 112, cols 2j..2j+2 <= 112) ----
    const int gw = 2 * j;
    float4 upL  = XV(oh,     gw + 1);
    float4 upR  = XV(oh,     gw + 2);
    float4 lfL  = XV(oh + 1, gw);
    float4 ctrL = XV(oh + 1, gw + 1);
    float4 ctrR = XV(oh + 1, gw + 2);   // right pixel's left tap == ctrL
    #undef XV

    float4 oL, oR;
#define COMP(f)                                                                \
    {                                                                          \
        float mxL = fmaxf(fmaxf(a00.f, a01.f), fmaxf(b00.f, b01.f));           \
        float mnL = (a00.f + a01.f + b00.f + b01.f) * 0.25f;                   \
        float dL = 2.0f * (fabsf(ctrL.f - upL.f) + fabsf(ctrL.f - lfL.f));     \
        oL.f = (dL > lam) ? mxL : mnL;                                         \
    }
    COMP(x) COMP(y) COMP(z) COMP(w)
#undef COMP
#define COMPR(f)                                                               \
    {                                                                          \
        float mxR = fmaxf(fmaxf(a02.f, a03.f), fmaxf(b02.f, b03.f));           \
        float mnR = (a02.f + a03.f + b02.f + b03.f) * 0.25f;                   \
        float dR = 2.0f * (fabsf(ctrR.f - upR.f) + fabsf(ctrR.f - ctrL.f));    \
        oR.f = (dR > lam) ? mxR : mnR;                                         \
    }
    COMPR(x) COMPR(y) COMPR(z) COMPR(w)
#undef COMPR

    const int pL = (b * OH_ + oh) * OW_ + 2 * j;     // left output pixel
    float4* o4 = (float4*)out;
    o4[pL * C4_ + c4]       = oL;
    o4[(pL + 1) * C4_ + c4] = oR;
}

extern "C" void kernel_launch(void* const* d_in, const int* in_sizes, int n_in,
                              void* d_out, int out_size)
{
    const float* x    = (const float*)d_in[0];
    const float* lamb = (const float*)d_in[1];
    if (n_in >= 2 && in_sizes[0] == 1) {             // guard against metadata order
        x    = (const float*)d_in[1];
        lamb = (const float*)d_in[0];
    }

    const int total = B_ * OH_ * OJ_ * C4_;          // 3,211,264 threads
    const int threads = 256;
    const int blocks = total / threads;              // 12544, exact
    gradpool_kernel<<<blocks, threads>>>(x, lamb, (float*)d_out);
}

// round 9
// speedup vs baseline: 1.0468x; 1.0468x over previous
#include <cuda_runtime.h>
#include <cuda_bf16.h>

// GradPooling: out[b,oh,ow,c] = sel ? max2x2 : mean2x2
//   sel = 2*(|x[oh+1,ow+1]-x[oh,ow+1]| + |x[oh+1,ow+1]-x[oh+1,ow]|) > lamb
//   pool window = x rows {2oh-1,2oh} x cols {2ow-1,2ow}, OOB -> 0.0
// x (32,224,224,64) f32 NHWC, out (32,112,112,64) f32.
//
// R6: one thread computes a 1x4 ow-QUAD (pixels 4j..4j+3) for 4 channels.
//     25 front-batched loads/thread (6.25/pixel), shared gradient left-taps,
//     no launch_bounds cap (avoid R5's spill regression). 16 warps/SM x 25
//     loads = 400 in flight, up 23% over R4 with zero local traffic.

#define B_   32
#define H_   224
#define W_   224
#define C_   64
#define OH_  112
#define OW_  112
#define OQ_  (OW_ / 4)   // 28 ow-quads
#define C4_  (C_ / 4)    // 16 float4 groups per pixel

__global__ __launch_bounds__(256)
void gradpool_kernel(const float* __restrict__ x,
                     const float* __restrict__ lamb,
                     float* __restrict__ out)
{
    const int tid = blockIdx.x * blockDim.x + threadIdx.x;

    const int c4 = tid & (C4_ - 1);
    int t = tid >> 4;
    const int j  = t % OQ_;  t /= OQ_;
    const int oh = t % OH_;
    const int b  = t / OH_;

    const float lam = __ldg(lamb);

    const float4* xb = (const float4*)(x) + (b * H_ * W_) * C4_ + c4;
    #define XV(h, w) xb[((h) * W_ + (w)) * C4_]

    // ---- pool window rows {2oh-1, 2oh}, cols {8j-1 .. 8j+6} ----
    const int h0 = 2 * oh - 1;
    const int h1 = 2 * oh;
    const int w0 = 8 * j - 1;

    const float4 z = make_float4(0.f, 0.f, 0.f, 0.f);
    float4 pa[8], pb[8];
    #pragma unroll
    for (int i = 1; i < 8; i++) pb[i] = XV(h1, w0 + i);
    pb[0] = z;
    if (j > 0) pb[0] = XV(h1, w0);
    if (oh > 0) {
        #pragma unroll
        for (int i = 1; i < 8; i++) pa[i] = XV(h0, w0 + i);
        pa[0] = z;
        if (j > 0) pa[0] = XV(h0, w0);
    } else {
        #pragma unroll
        for (int i = 0; i < 8; i++) pa[i] = z;
    }

    // ---- gradient taps: rows oh..oh+1 (<=112), cols 4j..4j+4 (<=112) ----
    const int gw = 4 * j;
    float4 up[4], cr[5];
    #pragma unroll
    for (int i = 0; i < 4; i++) up[i] = XV(oh, gw + 1 + i);
    #pragma unroll
    for (int i = 0; i < 5; i++) cr[i] = XV(oh + 1, gw + i);
    #undef XV

    float4 o[4];
    // pixel p (ow = 4j+p): pool cols pa/pb[2p], [2p+1];
    //   ctr = cr[p+1], up = up[p], left = cr[p]
#define COMP1(f, p)                                                            \
    {                                                                          \
        float mx = fmaxf(fmaxf(pa[2*(p)].f, pa[2*(p)+1].f),                    \
                         fmaxf(pb[2*(p)].f, pb[2*(p)+1].f));                   \
        float mn = (pa[2*(p)].f + pa[2*(p)+1].f +                              \
                    pb[2*(p)].f + pb[2*(p)+1].f) * 0.25f;                      \
        float d  = 2.0f * (fabsf(cr[(p)+1].f - up[(p)].f) +                    \
                           fabsf(cr[(p)+1].f - cr[(p)].f));                    \
        o[(p)].f = (d > lam) ? mx : mn;                                        \
    }
#define COMP4(f) COMP1(f,0) COMP1(f,1) COMP1(f,2) COMP1(f,3)
    COMP4(x) COMP4(y) COMP4(z) COMP4(w)
#undef COMP4
#undef COMP1

    const int base = ((b * OH_ + oh) * OW_ + 4 * j) * C4_ + c4;
    float4* o4 = (float4*)out;
    #pragma unroll
    for (int p = 0; p < 4; p++) o4[base + p * C4_] = o[p];
}

extern "C" void kernel_launch(void* const* d_in, const int* in_sizes, int n_in,
                              void* d_out, int out_size)
{
    const float* x    = (const float*)d_in[0];
    const float* lamb = (const float*)d_in[1];
    if (n_in >= 2 && in_sizes[0] == 1) {             // guard against metadata order
        x    = (const float*)d_in[1];
        lamb = (const float*)d_in[0];
    }

    const int total = B_ * OH_ * OQ_ * C4_;          // 1,605,632 threads
    const int threads = 256;
    const int blocks = total / threads;              // 6272, exact
    gradpool_kernel<<<blocks, threads>>>(x, lamb, (float*)d_out);
}

// round 11
// speedup vs baseline: 1.0786x; 1.0303x over previous
#include <cuda_runtime.h>
#include <cuda_bf16.h>

// GradPooling: out[b,oh,ow,c] = sel ? max2x2 : mean2x2
//   sel = 2*(|x[oh+1,ow+1]-x[oh,ow+1]| + |x[oh+1,ow+1]-x[oh+1,ow]|) > lamb
//   pool window = x rows {2oh-1,2oh} x cols {2ow-1,2ow}, OOB -> 0.0
// x (32,224,224,64) f32 NHWC, out (32,112,112,64) f32.
//
// R9: R4 body (ow-pair / 13 loads / 64 regs / 4 CTAs/SM) unchanged, wrapped in
//     a 4-iteration grid-stride loop (#pragma unroll 1 so the 13-load batches
//     stay separate). 4x warp lifetime -> less CTA churn / ramp exposure.

#define B_    32
#define H_    224
#define W_    224
#define C_    64
#define OH_   112
#define OW_   112
#define OJ_   (OW_ / 2)   // 56 ow-pairs
#define C4_   (C_ / 4)    // 16 float4 groups per pixel
#define ITER_ 4

__global__ __launch_bounds__(256, 4)
void gradpool_kernel(const float* __restrict__ x,
                     const float* __restrict__ lamb,
                     float* __restrict__ out)
{
    const int tid0 = blockIdx.x * blockDim.x + threadIdx.x;
    const int NT   = (B_ * OH_ * OJ_ * C4_) / ITER_;   // 802,816 (multiple of 16)
    const float lam = __ldg(lamb);
    float4* const o4 = (float4*)out;

    #pragma unroll 1
    for (int it = 0; it < ITER_; it++) {
        const int tid = tid0 + it * NT;

        const int c4 = tid & (C4_ - 1);
        int t = tid >> 4;
        const int j  = t % OJ_;  t /= OJ_;
        const int oh = t % OH_;
        const int b  = t / OH_;

        const float4* xb = (const float4*)(x) + (b * H_ * W_) * C4_ + c4;
        #define XV(h, w) xb[((h) * W_ + (w)) * C4_]

        // ---- pool windows: rows {2oh-1, 2oh}, cols {4j-1..4j+2} ----
        const int h0 = 2 * oh - 1;
        const int h1 = 2 * oh;
        const int w0 = 4 * j - 1;

        const float4 z = make_float4(0.f, 0.f, 0.f, 0.f);
        float4 a00 = z, a01, a02, a03;          // row h0
        float4 b00 = z, b01, b02, b03;          // row h1
        b01 = XV(h1, w0 + 1);
        b02 = XV(h1, w0 + 2);
        b03 = XV(h1, w0 + 3);
        if (j > 0) b00 = XV(h1, w0);
        if (oh > 0) {
            a01 = XV(h0, w0 + 1);
            a02 = XV(h0, w0 + 2);
            a03 = XV(h0, w0 + 3);
            if (j > 0) a00 = XV(h0, w0);
        } else {
            a01 = z; a02 = z; a03 = z;
        }

        // ---- gradient taps (rows oh..oh+1 <= 112, cols 2j..2j+2 <= 112) ----
        const int gw = 2 * j;
        float4 upL  = XV(oh,     gw + 1);
        float4 upR  = XV(oh,     gw + 2);
        float4 lfL  = XV(oh + 1, gw);
        float4 ctrL = XV(oh + 1, gw + 1);
        float4 ctrR = XV(oh + 1, gw + 2);   // right pixel's left tap == ctrL
        #undef XV

        float4 oL, oR;
#define COMP(f)                                                                \
        {                                                                      \
            float mxL = fmaxf(fmaxf(a00.f, a01.f), fmaxf(b00.f, b01.f));       \
            float mnL = (a00.f + a01.f + b00.f + b01.f) * 0.25f;               \
            float dL = 2.0f * (fabsf(ctrL.f - upL.f) + fabsf(ctrL.f - lfL.f)); \
            oL.f = (dL > lam) ? mxL : mnL;                                     \
        }
        COMP(x) COMP(y) COMP(z) COMP(w)
#undef COMP
#define COMPR(f)                                                               \
        {                                                                      \
            float mxR = fmaxf(fmaxf(a02.f, a03.f), fmaxf(b02.f, b03.f));       \
            float mnR = (a02.f + a03.f + b02.f + b03.f) * 0.25f;               \
            float dR = 2.0f * (fabsf(ctrR.f - upR.f) + fabsf(ctrR.f - ctrL.f));\
            oR.f = (dR > lam) ? mxR : mnR;                                     \
        }
        COMPR(x) COMPR(y) COMPR(z) COMPR(w)
#undef COMPR

        const int pL = (b * OH_ + oh) * OW_ + 2 * j;     // left output pixel
        o4[pL * C4_ + c4]       = oL;
        o4[(pL + 1) * C4_ + c4] = oR;
    }
}

extern "C" void kernel_launch(void* const* d_in, const int* in_sizes, int n_in,
                              void* d_out, int out_size)
{
    const float* x    = (const float*)d_in[0];
    const float* lamb = (const float*)d_in[1];
    if (n_in >= 2 && in_sizes[0] == 1) {             // guard against metadata order
        x    = (const float*)d_in[1];
        lamb = (const float*)d_in[0];
    }

    const int total_threads = (B_ * OH_ * OJ_ * C4_) / ITER_;  // 802,816
    const int threads = 256;
    const int blocks = total_threads / threads;                // 3136, exact
    gradpool_kernel<<<blocks, threads>>>(x, lamb, (float*)d_out);
}